// round 15
// baseline (speedup 1.0000x reference)
#include <cuda_runtime.h>
#include <cuda_bf16.h>
#include <math.h>

#define NBATCH 16
#define CI 32
#define CO 64
#define HH 128
#define WW 128
#define DS 5
#define KK 800     // CI*DS*DS
#define BS 100     // Cholesky panel
#define SB 20      // potrf sub-block
#define NSTEP 8    // KK/BS
#define NBH 8      // batches per stream

// ---------------- scratch ----------
__device__ float g_R[NBATCH][CI][CI][9][9];
__device__ float g_Q[NBATCH][KK][KK];
__device__ float g_P[NBATCH][KK][CO];
__device__ float g_Linv[NSTEP][NBATCH][BS][BS];

// ===========================================================================
// Kernel 1 (v4): gram
// ===========================================================================
__global__ __launch_bounds__(256) void gram_kernel(const float* __restrict__ x)
{
    int n = blockIdx.y;
    int p = blockIdx.x;
    int a = 0, rem = p;
    while (rem >= CI - a) { rem -= CI - a; a++; }
    int b = a + rem;

    const float* __restrict__ xa = x + ((size_t)n * CI + a) * (HH * WW);
    const float* __restrict__ xb = x + ((size_t)n * CI + b) * (HH * WW);

    __shared__ float sxa[32][132];
    __shared__ float sxb[40][148];
    __shared__ float sred[8][81];

    int tid  = threadIdx.x;
    int lane = tid & 31;
    int wid  = tid >> 5;
    int ty = (tid & 1) + 2 * (tid >> 5);
    int tx = (tid >> 1) & 15;
    int c0 = tx * 8;

    for (int i = tid; i < 40 * 5; i += 256) {
        int rr = i / 5, e = i - rr * 5;
        int col = (e < 2) ? e * 4 : 136 + (e - 2) * 4;
        *(float4*)(&sxb[rr][col]) = make_float4(0.f, 0.f, 0.f, 0.f);
    }

    float acc[81];
#pragma unroll
    for (int q = 0; q < 81; q++) acc[q] = 0.f;

    for (int s = 0; s < 4; s++) {
        int r0 = s * 32;
        for (int i = tid; i < 1024; i += 256) {
            int rr = i >> 5, q = i & 31;
            *(float4*)(&sxa[rr][q * 4]) =
                *((const float4*)(xa + (size_t)(r0 + rr) * WW) + q);
        }
        for (int i = tid; i < 1280; i += 256) {
            int rr = i >> 5, q = i & 31;
            int gr = r0 + rr - 4;
            float4 v = make_float4(0.f, 0.f, 0.f, 0.f);
            if (gr >= 0 && gr < HH)
                v = *((const float4*)(xb + (size_t)gr * WW) + q);
            *(float4*)(&sxb[rr][8 + q * 4]) = v;
        }
        __syncthreads();

#pragma unroll
        for (int half = 0; half < 2; half++) {
            int r = ty + half * 16;
            float xav[8];
            {
                const float4* rowp = (const float4*)(&sxa[r][c0]);
                float4 v0 = rowp[0], v1 = rowp[1];
                xav[0] = v0.x; xav[1] = v0.y; xav[2] = v0.z; xav[3] = v0.w;
                xav[4] = v1.x; xav[5] = v1.y; xav[6] = v1.z; xav[7] = v1.w;
            }
#pragma unroll
            for (int du = 0; du < 9; du++) {
                float xbv[16];
                const float4* row = (const float4*)(&sxb[r + du][c0 + 4]);
#pragma unroll
                for (int q4 = 0; q4 < 4; q4++) {
                    float4 v = row[q4];
                    xbv[q4 * 4 + 0] = v.x; xbv[q4 * 4 + 1] = v.y;
                    xbv[q4 * 4 + 2] = v.z; xbv[q4 * 4 + 3] = v.w;
                }
#pragma unroll
                for (int t = 0; t < 8; t++)
#pragma unroll
                    for (int dv = 0; dv < 9; dv++)
                        acc[du * 9 + dv] += xav[t] * xbv[t + dv];
            }
        }
        __syncthreads();
    }

#pragma unroll
    for (int q = 0; q < 81; q++) {
        float v = acc[q];
        for (int o = 16; o; o >>= 1) v += __shfl_down_sync(0xffffffffu, v, o);
        if (lane == 0) sred[wid][q] = v;
    }
    __syncthreads();
    if (tid < 81) {
        float v = 0.f;
#pragma unroll
        for (int w = 0; w < 8; w++) v += sred[w][tid];
        int u = tid / 9, vv = tid - u * 9;
        g_R[n][a][b][u][vv] = v;
        g_R[n][b][a][8 - u][8 - vv] = v;
    }
}

// ===========================================================================
// Kernel 2 (v4): scorr
// ===========================================================================
__global__ __launch_bounds__(256) void scorr_kernel(const float* __restrict__ x,
                                                    const float* __restrict__ y,
                                                    const float* __restrict__ d,
                                                    const float* __restrict__ alpha,
                                                    const float* __restrict__ regp)
{
    int n  = blockIdx.y;
    int b  = blockIdx.x & 31;
    int o0 = (blockIdx.x >> 5) * 4;

    const float* __restrict__ xb = x + ((size_t)n * CI + b) * (HH * WW);
    const float* __restrict__ yb = y + ((size_t)n * CO + o0) * (HH * WW);

    __shared__ float sya[4][16][132];
    __shared__ float sxb[20][148];
    __shared__ float sred[8][100];

    int tid  = threadIdx.x;
    int lane = tid & 31;
    int wid  = tid >> 5;
    int ty = (tid & 1) + 2 * (tid >> 5);
    int tx = (tid >> 1) & 15;
    int c0 = tx * 8;
    int fy = tid >> 4, fx = tid & 15;

    for (int i = tid; i < 20 * 5; i += 256) {
        int rr = i / 5, e = i - rr * 5;
        int col = (e < 2) ? e * 4 : 136 + (e - 2) * 4;
        *(float4*)(&sxb[rr][col]) = make_float4(0.f, 0.f, 0.f, 0.f);
    }

    float acc[100];
#pragma unroll
    for (int q = 0; q < 100; q++) acc[q] = 0.f;

    for (int s = 0; s < 8; s++) {
        int r0 = s * 16;
#pragma unroll
        for (int o = 0; o < 4; o++) {
            const float4* src = (const float4*)(yb + (size_t)o * (HH * WW) + (size_t)(r0 + fy) * WW);
            float4* dst = (float4*)(&sya[o][fy][0]);
            dst[fx * 2]     = src[fx * 2];
            dst[fx * 2 + 1] = src[fx * 2 + 1];
        }
        for (int i = tid; i < 640; i += 256) {
            int rr = i >> 5, q = i & 31;
            int gr = r0 + rr - 2;
            float4 v = make_float4(0.f, 0.f, 0.f, 0.f);
            if (gr >= 0 && gr < HH)
                v = *((const float4*)(xb + (size_t)gr * WW) + q);
            *(float4*)(&sxb[rr][8 + q * 4]) = v;
        }
        __syncthreads();

#pragma unroll
        for (int o = 0; o < 4; o++) {
            float yav[8];
            {
                const float4* rowp = (const float4*)(&sya[o][ty][c0]);
                float4 v0 = rowp[0], v1 = rowp[1];
                yav[0] = v0.x; yav[1] = v0.y; yav[2] = v0.z; yav[3] = v0.w;
                yav[4] = v1.x; yav[5] = v1.y; yav[6] = v1.z; yav[7] = v1.w;
            }
#pragma unroll
            for (int du = 0; du < 5; du++) {
                float xraw[16];
                const float4* row = (const float4*)(&sxb[ty + du][c0 + 4]);
#pragma unroll
                for (int q4 = 0; q4 < 4; q4++) {
                    float4 v = row[q4];
                    xraw[q4 * 4 + 0] = v.x; xraw[q4 * 4 + 1] = v.y;
                    xraw[q4 * 4 + 2] = v.z; xraw[q4 * 4 + 3] = v.w;
                }
#pragma unroll
                for (int t = 0; t < 8; t++)
#pragma unroll
                    for (int dv = 0; dv < 5; dv++)
                        acc[o * 25 + du * 5 + dv] += yav[t] * xraw[t + dv + 2];
            }
        }
        __syncthreads();
    }

#pragma unroll
    for (int q = 0; q < 100; q++) {
        float v = acc[q];
        for (int oo = 16; oo; oo >>= 1) v += __shfl_down_sync(0xffffffffu, v, oo);
        if (lane == 0) sred[wid][q] = v;
    }
    __syncthreads();
    if (tid < 100) {
        float v = 0.f;
#pragma unroll
        for (int w = 0; w < 8; w++) v += sred[w][tid];
        int o = tid / 25, q = tid - o * 25;
        int k = b * 25 + q;
        float an = alpha[n] * ((float)(HH * WW) * regp[0] / (float)(DS * DS * CI));
        g_P[n][k][o0 + o] = v + an * d[((size_t)n * CO + o0 + o) * KK + k];
    }
}

// ===========================================================================
// Kernel 3 (v2): assembleQ
// ===========================================================================
__global__ __launch_bounds__(256) void assembleQ_kernel(const float* __restrict__ alpha,
                                                        const float* __restrict__ regp)
{
    int n = blockIdx.y;
    int a = blockIdx.x;
    __shared__ float Rs[CI][81];

    int tid = threadIdx.x;
    const float* rsrc = &g_R[n][a][0][0][0];
    for (int i = tid; i < CI * 81; i += 256)
        Rs[i / 81][i - (i / 81) * 81] = rsrc[i];
    __syncthreads();

    float an = alpha[n] * ((float)(HH * WW) * regp[0] / (float)(DS * DS * CI));
#pragma unroll
    for (int r = 0; r < 5; r++) {
#pragma unroll
        for (int s5 = 0; s5 < 5; s5++) {
            int k1 = a * 25 + r * 5 + s5;
            for (int k2 = tid; k2 <= k1; k2 += 256) {
                int bb = k2 / 25, rm = k2 - bb * 25;
                int pp = rm / 5, tt = rm - pp * 5;
                float v = Rs[bb][(pp - r + 4) * 9 + (tt - s5 + 4)];
                if (k2 == k1) v += an;
                g_Q[n][k1][k2] = v;
            }
        }
    }
}

// ===========================================================================
// potrf v5 (+nbase)
// ===========================================================================
__global__ __launch_bounds__(256) void potrf_kernel(int k0, int s, int nbase)
{
    int n = nbase + blockIdx.x;
    extern __shared__ float sh[];
    float (*A)[BS + 1] = (float(*)[BS + 1])sh;
    float (*V)[BS + 1] = (float(*)[BS + 1])(sh + BS * (BS + 1));
    __shared__ float dinv[BS];
    __shared__ float colb[32];
    __shared__ float Dv[5][SB][SB];
    __shared__ float Bt[4][SB][SB];

    int tid  = threadIdx.x;
    int lane = tid & 31;
    int wid  = tid >> 5;

    for (int idx = tid; idx < BS * BS; idx += 256) {
        int i = idx / BS, j = idx - i * BS;
        A[i][j] = g_Q[n][k0 + i][k0 + j];
    }
    __syncthreads();

    for (int p = 0; p < BS / SB; p++) {
        int c0 = p * SB;

        if (wid == 0) {
            float r[SB];
            if (lane < SB) {
#pragma unroll
                for (int j = 0; j < SB; j++) r[j] = A[c0 + lane][c0 + j];
            }
#pragma unroll
            for (int j = 0; j < SB; j++) {
                float ajj = __shfl_sync(0xffffffffu, r[j], j);
                float dd = rsqrtf(ajj);
                if (lane == j) dinv[c0 + j] = dd;
                if (lane >= j && lane < SB) r[j] *= dd;
                colb[lane] = r[j];
                __syncwarp();
#pragma unroll
                for (int k = j + 1; k < SB; k++)
                    if (lane >= k) r[k] -= r[j] * colb[k];
                __syncwarp();
            }
            if (lane < SB) {
#pragma unroll
                for (int j = 0; j < SB; j++)
                    if (j <= lane) A[c0 + lane][c0 + j] = r[j];
            }
        }
        __syncthreads();

        if (wid == 0) {
            if (lane < SB) {
                int c = lane;
                float w[SB];
#pragma unroll
                for (int r2 = 0; r2 < SB; r2++) {
                    float t = (r2 == c) ? 1.f : 0.f;
#pragma unroll
                    for (int m = 0; m < SB; m++)
                        if (m < r2) t -= A[c0 + r2][c0 + m] * w[m];
                    w[r2] = t * dinv[c0 + r2];
                }
#pragma unroll
                for (int r2 = 0; r2 < SB; r2++) Dv[p][r2][c] = w[r2];
            }
        } else {
            int rr = c0 + SB + (tid - 32);
            if (rr < BS) {
                float v[SB];
#pragma unroll
                for (int j = 0; j < SB; j++) v[j] = A[rr][c0 + j];
#pragma unroll
                for (int j = 0; j < SB; j++) {
                    float t = v[j];
#pragma unroll
                    for (int m = 0; m < SB; m++)
                        if (m < j) t -= A[c0 + j][c0 + m] * v[m];
                    v[j] = t * dinv[c0 + j];
                }
#pragma unroll
                for (int j = 0; j < SB; j++) A[rr][c0 + j] = v[j];
            }
        }
        __syncthreads();

        int m = BS - c0 - SB;
        if (m > 0) {
            int tr = tid >> 4, tc = tid & 15;
            float c[5][5];
#pragma unroll
            for (int i = 0; i < 5; i++)
#pragma unroll
                for (int j = 0; j < 5; j++) c[i][j] = 0.f;
#pragma unroll
            for (int k = 0; k < SB; k++) {
                float ra[5], rb[5];
#pragma unroll
                for (int ii = 0; ii < 5; ii++) {
                    int row = c0 + SB + tr + ii * 16;
                    ra[ii] = (row < BS) ? A[row][c0 + k] : 0.f;
                }
#pragma unroll
                for (int jj = 0; jj < 5; jj++) {
                    int col = c0 + SB + tc + jj * 16;
                    rb[jj] = (col < BS) ? A[col][c0 + k] : 0.f;
                }
#pragma unroll
                for (int ii = 0; ii < 5; ii++)
#pragma unroll
                    for (int jj = 0; jj < 5; jj++)
                        c[ii][jj] += ra[ii] * rb[jj];
            }
#pragma unroll
            for (int ii = 0; ii < 5; ii++) {
                int row = c0 + SB + tr + ii * 16;
                if (row < BS) {
#pragma unroll
                    for (int jj = 0; jj < 5; jj++) {
                        int col = c0 + SB + tc + jj * 16;
                        if (col < BS) A[row][col] -= c[ii][jj];
                    }
                }
            }
        }
        __syncthreads();
    }

    for (int idx = tid; idx < 5 * SB * SB; idx += 256) {
        int q = idx / (SB * SB), r2 = (idx / SB) % SB, cc = idx % SB;
        V[q * SB + r2][q * SB + cc] = Dv[q][r2][cc];
    }
    __syncthreads();
    for (int p = 1; p < BS / SB; p++) {
        for (int idx = tid; idx < p * SB * SB; idx += 256) {
            int q = idx / (SB * SB), r2 = (idx / SB) % SB, cc = idx % SB;
            float t = 0.f;
            for (int mm = q; mm < p; mm++) {
#pragma unroll
                for (int k = 0; k < SB; k++)
                    t += A[p * SB + r2][mm * SB + k] * V[mm * SB + k][q * SB + cc];
            }
            Bt[q][r2][cc] = t;
        }
        __syncthreads();
        for (int idx = tid; idx < p * SB * SB; idx += 256) {
            int q = idx / (SB * SB), r2 = (idx / SB) % SB, cc = idx % SB;
            float t = 0.f;
#pragma unroll
            for (int k = 0; k < SB; k++)
                t += Dv[p][r2][k] * Bt[q][k][cc];
            V[p * SB + r2][q * SB + cc] = -t;
        }
        __syncthreads();
    }

    for (int idx = tid; idx < BS * BS; idx += 256) {
        int i = idx / BS, j = idx - i * BS;
        if (j <= i) g_Q[n][k0 + i][k0 + j] = A[i][j];
        g_Linv[s][n][i][j] = (j <= i) ? V[i][j] : 0.f;
    }
}

// ===========================================================================
// trsm (Q tiles only): A21 <- A21 * Linv^T
// ===========================================================================
__global__ __launch_bounds__(256) void trsm_gemm(int k0, int s, int nbase)
{
    int n = nbase + blockIdx.y;
    int p = blockIdx.x;

    extern __shared__ float sh[];
    float (*Li)[BS + 1] = (float(*)[BS + 1])sh;
    float (*Ta)[BS + 1] = (float(*)[BS + 1])(sh + BS * (BS + 1));

    int tid = threadIdx.x;
    int tr = tid >> 4, tc = tid & 15;

    for (int idx = tid; idx < BS * BS; idx += 256) {
        int i = idx / BS, j = idx - i * BS;
        Li[i][j] = g_Linv[s][n][i][j];
    }

    int rbase = k0 + BS + p * 64;
    for (int idx = tid; idx < 64 * BS; idx += 256) {
        int rr = idx / BS, k = idx - rr * BS;
        Ta[rr][k] = (rbase + rr < KK) ? g_Q[n][rbase + rr][k0 + k] : 0.f;
    }
    __syncthreads();

    float c[4][7];
#pragma unroll
    for (int i = 0; i < 4; i++)
#pragma unroll
        for (int j = 0; j < 7; j++) c[i][j] = 0.f;
#pragma unroll 4
    for (int k = 0; k < BS; k++) {
        float ra[4], rb[7];
#pragma unroll
        for (int ii = 0; ii < 4; ii++) ra[ii] = Ta[tr + 16 * ii][k];
#pragma unroll
        for (int jj = 0; jj < 7; jj++) {
            int j = tc + 16 * jj;
            rb[jj] = (j < BS) ? Li[j][k] : 0.f;
        }
#pragma unroll
        for (int ii = 0; ii < 4; ii++)
#pragma unroll
            for (int jj = 0; jj < 7; jj++)
                c[ii][jj] += ra[ii] * rb[jj];
    }
#pragma unroll
    for (int ii = 0; ii < 4; ii++) {
        int gr = rbase + tr + 16 * ii;
        if (gr < KK) {
#pragma unroll
            for (int jj = 0; jj < 7; jj++) {
                int j = tc + 16 * jj;
                if (j < BS) g_Q[n][gr][k0 + j] = c[ii][jj];
            }
        }
    }
}

// ===========================================================================
// fwd_gemm: Z_panel <- Linv * P_panel   (P-branch of old trsm, standalone)
// ===========================================================================
__global__ __launch_bounds__(256) void fwd_gemm(int k0, int s, int nbase)
{
    int n = nbase + blockIdx.x;

    extern __shared__ float sh[];
    float (*Li)[BS + 1] = (float(*)[BS + 1])sh;
    float (*Tp)[CO + 1] = (float(*)[CO + 1])(sh + BS * (BS + 1));

    int tid = threadIdx.x;
    int tr = tid >> 4, tc = tid & 15;

    for (int idx = tid; idx < BS * BS; idx += 256) {
        int i = idx / BS, j = idx - i * BS;
        Li[i][j] = g_Linv[s][n][i][j];
    }
    for (int idx = tid; idx < BS * CO; idx += 256) {
        int k = idx >> 6, cc = idx & 63;
        Tp[k][cc] = g_P[n][k0 + k][cc];
    }
    __syncthreads();

    float c[7][4];
#pragma unroll
    for (int i = 0; i < 7; i++)
#pragma unroll
        for (int j = 0; j < 4; j++) c[i][j] = 0.f;
#pragma unroll 4
    for (int k = 0; k < BS; k++) {
        float ra[7], rb[4];
#pragma unroll
        for (int ii = 0; ii < 7; ii++) {
            int i = tr + 16 * ii;
            ra[ii] = (i < BS) ? Li[i][k] : 0.f;
        }
#pragma unroll
        for (int jj = 0; jj < 4; jj++) rb[jj] = Tp[k][tc + 16 * jj];
#pragma unroll
        for (int ii = 0; ii < 7; ii++)
#pragma unroll
            for (int jj = 0; jj < 4; jj++)
                c[ii][jj] += ra[ii] * rb[jj];
    }
#pragma unroll
    for (int ii = 0; ii < 7; ii++) {
        int i = tr + 16 * ii;
        if (i < BS) {
#pragma unroll
            for (int jj = 0; jj < 4; jj++)
                g_P[n][k0 + i][tc + 16 * jj] = c[ii][jj];
        }
    }
}

// ===========================================================================
// fsolve_update: P[off..] -= L[off.., k0:k0+100] * Z_panel  (old syrk pmode)
// ===========================================================================
__global__ __launch_bounds__(256) void fsolve_update(int k0, int nbase)
{
    int off = k0 + BS;
    int n = nbase + blockIdx.y;
    int rbase = off + blockIdx.x * 64;

    __shared__ float LA[64][21];
    __shared__ float LB[64][21];
    int tid = threadIdx.x;
    int txx = tid & 15, tyy = tid >> 4;

    float c[4][4];
#pragma unroll
    for (int i = 0; i < 4; i++)
#pragma unroll
        for (int j = 0; j < 4; j++) c[i][j] = 0.f;

    for (int kk = 0; kk < BS; kk += 20) {
        for (int idx = tid; idx < 64 * 20; idx += 256) {
            int rr = idx / 20, k = idx - rr * 20;
            LA[rr][k] = (rbase + rr < KK) ? g_Q[n][rbase + rr][k0 + kk + k] : 0.f;
        }
        for (int idx = tid; idx < 20 * 64; idx += 256) {
            int k = idx >> 6, cc = idx & 63;
            LB[cc][k] = g_P[n][k0 + kk + k][cc];
        }
        __syncthreads();
#pragma unroll
        for (int k = 0; k < 20; k++) {
            float ra[4], rb[4];
#pragma unroll
            for (int i = 0; i < 4; i++) ra[i] = LA[tyy * 4 + i][k];
#pragma unroll
            for (int j = 0; j < 4; j++) rb[j] = LB[txx * 4 + j][k];
#pragma unroll
            for (int i = 0; i < 4; i++)
#pragma unroll
                for (int j = 0; j < 4; j++) c[i][j] += ra[i] * rb[j];
        }
        __syncthreads();
    }
#pragma unroll
    for (int i = 0; i < 4; i++) {
        int gr = rbase + tyy * 4 + i;
        if (gr < KK) {
#pragma unroll
            for (int j = 0; j < 4; j++)
                g_P[n][gr][txx * 4 + j] -= c[i][j];
        }
    }
}

// ===========================================================================
// syrk (Q tiles only): A22 -= L21*L21^T
// ===========================================================================
__global__ __launch_bounds__(256) void syrk_kernel(int k0, int nbase)
{
    int off = k0 + BS;
    int m = KK - off;
    int nt = (m + 63) >> 6;
    int n = nbase + blockIdx.y;
    int p = blockIdx.x;

    __shared__ float LA[64][21];
    __shared__ float LB[64][21];
    int tid = threadIdx.x;
    int txx = tid & 15, tyy = tid >> 4;

    int tj = 0;
    while (p >= nt - tj) { p -= nt - tj; tj++; }
    int ti = tj + p;

    float c[4][4];
#pragma unroll
    for (int i = 0; i < 4; i++)
#pragma unroll
        for (int j = 0; j < 4; j++) c[i][j] = 0.f;

    int rbase = off + ti * 64;
    int cbase = off + tj * 64;

    for (int kk = 0; kk < BS; kk += 20) {
        for (int idx = tid; idx < 64 * 20; idx += 256) {
            int rr = idx / 20, k = idx - rr * 20;
            LA[rr][k] = (rbase + rr < KK) ? g_Q[n][rbase + rr][k0 + kk + k] : 0.f;
        }
        for (int idx = tid; idx < 64 * 20; idx += 256) {
            int rr = idx / 20, k = idx - rr * 20;
            LB[rr][k] = (cbase + rr < KK) ? g_Q[n][cbase + rr][k0 + kk + k] : 0.f;
        }
        __syncthreads();
#pragma unroll
        for (int k = 0; k < 20; k++) {
            float ra[4], rb[4];
#pragma unroll
            for (int i = 0; i < 4; i++) ra[i] = LA[tyy * 4 + i][k];
#pragma unroll
            for (int j = 0; j < 4; j++) rb[j] = LB[txx * 4 + j][k];
#pragma unroll
            for (int i = 0; i < 4; i++)
#pragma unroll
                for (int j = 0; j < 4; j++) c[i][j] += ra[i] * rb[j];
        }
        __syncthreads();
    }
#pragma unroll
    for (int i = 0; i < 4; i++) {
        int gr = rbase + tyy * 4 + i;
        if (gr < KK) {
#pragma unroll
            for (int j = 0; j < 4; j++) {
                int gc = cbase + txx * 4 + j;
                if (gc < KK) g_Q[n][gr][gc] -= c[i][j];
            }
        }
    }
}

// ===========================================================================
// backward diag solve as GEMM (+nbase)
// ===========================================================================
__global__ __launch_bounds__(256) void bwd_gemm(int k0, int s, int nbase)
{
    int n = nbase + blockIdx.y;
    int half = blockIdx.x;

    extern __shared__ float sh[];
    float (*Li)[BS + 1] = (float(*)[BS + 1])sh;
    float (*Zp)[33]     = (float(*)[33])(sh + BS * (BS + 1));

    int tid = threadIdx.x;
    int tr = tid >> 4, tc = tid & 15;

    for (int idx = tid; idx < BS * BS; idx += 256) {
        int i = idx / BS, j = idx - i * BS;
        Li[i][j] = g_Linv[s][n][i][j];
    }
    for (int idx = tid; idx < BS * 32; idx += 256) {
        int k = idx >> 5, cc = idx & 31;
        Zp[k][cc] = g_P[n][k0 + k][half * 32 + cc];
    }
    __syncthreads();

    float c[7][2];
#pragma unroll
    for (int i = 0; i < 7; i++)
#pragma unroll
        for (int j = 0; j < 2; j++) c[i][j] = 0.f;
#pragma unroll 4
    for (int k = 0; k < BS; k++) {
        float ra[7], rb[2];
#pragma unroll
        for (int ii = 0; ii < 7; ii++) {
            int i = tr + 16 * ii;
            ra[ii] = (i < BS) ? Li[k][i] : 0.f;
        }
#pragma unroll
        for (int jj = 0; jj < 2; jj++) rb[jj] = Zp[k][tc + 16 * jj];
#pragma unroll
        for (int ii = 0; ii < 7; ii++)
#pragma unroll
            for (int jj = 0; jj < 2; jj++)
                c[ii][jj] += ra[ii] * rb[jj];
    }
#pragma unroll
    for (int ii = 0; ii < 7; ii++) {
        int i = tr + 16 * ii;
        if (i < BS) {
#pragma unroll
            for (int jj = 0; jj < 2; jj++)
                g_P[n][k0 + i][half * 32 + tc + 16 * jj] = c[ii][jj];
        }
    }
}

// backward update (+nbase)
__global__ __launch_bounds__(256) void bsolve_update_kernel(int k0, int nbase)
{
    int n = nbase + blockIdx.y;
    int rbase = blockIdx.x * 64;

    __shared__ float AT[20][65];
    __shared__ float BB[20][65];
    int tid = threadIdx.x;
    int txx = tid & 15, tyy = tid >> 4;

    float c[4][4];
#pragma unroll
    for (int i = 0; i < 4; i++)
#pragma unroll
        for (int j = 0; j < 4; j++) c[i][j] = 0.f;

    for (int kk = 0; kk < BS; kk += 20) {
        for (int idx = tid; idx < 20 * 64; idx += 256) {
            int k = idx >> 6, rl = idx & 63;
            AT[k][rl] = g_Q[n][k0 + kk + k][rbase + rl];
        }
        for (int idx = tid; idx < 20 * 64; idx += 256) {
            int k = idx >> 6, cc = idx & 63;
            BB[k][cc] = g_P[n][k0 + kk + k][cc];
        }
        __syncthreads();
#pragma unroll
        for (int k = 0; k < 20; k++) {
            float ra[4], rb[4];
#pragma unroll
            for (int i = 0; i < 4; i++) ra[i] = AT[k][tyy * 4 + i];
#pragma unroll
            for (int j = 0; j < 4; j++) rb[j] = BB[k][txx * 4 + j];
#pragma unroll
            for (int i = 0; i < 4; i++)
#pragma unroll
                for (int j = 0; j < 4; j++) c[i][j] += ra[i] * rb[j];
        }
        __syncthreads();
    }
#pragma unroll
    for (int i = 0; i < 4; i++) {
        int gr = rbase + tyy * 4 + i;
        if (gr < k0) {
#pragma unroll
            for (int j = 0; j < 4; j++)
                g_P[n][gr][txx * 4 + j] -= c[i][j];
        }
    }
}

// final transpose: out[n][o][k] = P[n][k][o]
__global__ __launch_bounds__(256) void output_kernel(float* __restrict__ out)
{
    __shared__ float t[32][33];
    int n  = blockIdx.z;
    int kb = blockIdx.x * 32;
    int ob = blockIdx.y * 32;
    int tx = threadIdx.x & 31, ty4 = threadIdx.x >> 5;

    for (int i = ty4; i < 32; i += 8)
        t[i][tx] = g_P[n][kb + i][ob + tx];
    __syncthreads();
    for (int i = ty4; i < 32; i += 8)
        out[((size_t)n * CO + ob + i) * KK + kb + tx] = t[tx][i];
}

// ===========================================================================
static void run_factor(cudaStream_t st, int nbase)
{
    for (int s = 0; s < NSTEP; s++) {
        int k0 = s * BS;
        potrf_kernel<<<NBH, 256, 2 * BS * (BS + 1) * 4, st>>>(k0, s, nbase);
        int rows = KK - k0 - BS;
        if (rows > 0) {
            int rowTiles = (rows + 63) / 64;
            trsm_gemm<<<dim3(rowTiles, NBH), 256, (BS * (BS + 1) + BS * (CO + 1)) * 4, st>>>(k0, s, nbase);
            int nt = rowTiles;
            syrk_kernel<<<dim3(nt * (nt + 1) / 2, NBH), 256, 0, st>>>(k0, nbase);
        }
    }
}

static void run_solve(cudaStream_t st, int nbase)
{
    // forward substitution via Linv GEMMs
    for (int s = 0; s < NSTEP; s++) {
        int k0 = s * BS;
        fwd_gemm<<<NBH, 256, (BS * (BS + 1) + BS * (CO + 1)) * 4, st>>>(k0, s, nbase);
        int rows = KK - k0 - BS;
        if (rows > 0)
            fsolve_update<<<dim3((rows + 63) / 64, NBH), 256, 0, st>>>(k0, nbase);
    }
    // backward substitution
    for (int s = NSTEP - 1; s >= 0; s--) {
        int k0 = s * BS;
        bwd_gemm<<<dim3(2, NBH), 256, (BS * (BS + 1) + BS * 33) * 4, st>>>(k0, s, nbase);
        if (k0 > 0)
            bsolve_update_kernel<<<dim3((k0 + 63) / 64, NBH), 256, 0, st>>>(k0, nbase);
    }
}

extern "C" void kernel_launch(void* const* d_in, const int* in_sizes, int n_in,
                              void* d_out, int out_size)
{
    const float* x     = (const float*)d_in[0];
    const float* d     = (const float*)d_in[1];
    const float* y     = (const float*)d_in[2];
    const float* alpha = (const float*)d_in[3];
    const float* regp  = (const float*)d_in[4];

    static int init_done = 0;
    static cudaStream_t st1, st2, st3;
    static cudaEvent_t evFork, evS, evJ1, evJ2;
    if (!init_done) {
        cudaFuncSetAttribute(potrf_kernel, cudaFuncAttributeMaxDynamicSharedMemorySize, 2 * BS * (BS + 1) * 4);
        cudaFuncSetAttribute(trsm_gemm,    cudaFuncAttributeMaxDynamicSharedMemorySize, (BS * (BS + 1) + BS * (CO + 1)) * 4);
        cudaFuncSetAttribute(fwd_gemm,     cudaFuncAttributeMaxDynamicSharedMemorySize, (BS * (BS + 1) + BS * (CO + 1)) * 4);
        cudaFuncSetAttribute(bwd_gemm,     cudaFuncAttributeMaxDynamicSharedMemorySize, (BS * (BS + 1) + BS * 33) * 4);
        cudaStreamCreateWithFlags(&st1, cudaStreamNonBlocking);
        cudaStreamCreateWithFlags(&st2, cudaStreamNonBlocking);
        cudaStreamCreateWithFlags(&st3, cudaStreamNonBlocking);
        cudaEventCreateWithFlags(&evFork, cudaEventDisableTiming);
        cudaEventCreateWithFlags(&evS,    cudaEventDisableTiming);
        cudaEventCreateWithFlags(&evJ1,   cudaEventDisableTiming);
        cudaEventCreateWithFlags(&evJ2,   cudaEventDisableTiming);
        init_done = 1;
    }

    // Q path prerequisites on default stream
    gram_kernel <<<dim3(528, NBATCH), 256>>>(x);
    assembleQ_kernel<<<dim3(CI, NBATCH), 256>>>(alpha, regp);

    cudaEventRecord(evFork, 0);
    cudaStreamWaitEvent(st1, evFork, 0);
    cudaStreamWaitEvent(st2, evFork, 0);
    cudaStreamWaitEvent(st3, evFork, 0);

    // scorr (produces P) runs concurrently with the factorization chains
    scorr_kernel<<<dim3(512, NBATCH), 256, 0, st3>>>(x, y, d, alpha, regp);
    cudaEventRecord(evS, st3);

    run_factor(st1, 0);
    run_factor(st2, NBH);

    // solves need P
    cudaStreamWaitEvent(st1, evS, 0);
    cudaStreamWaitEvent(st2, evS, 0);
    run_solve(st1, 0);
    run_solve(st2, NBH);

    cudaEventRecord(evJ1, st1);
    cudaEventRecord(evJ2, st2);
    cudaStreamWaitEvent(0, evJ1, 0);
    cudaStreamWaitEvent(0, evJ2, 0);

    output_kernel<<<dim3(KK / 32, CO / 32, NBATCH), 256>>>((float*)d_out);
}

// round 16
// speedup vs baseline: 1.0798x; 1.0798x over previous
#include <cuda_runtime.h>
#include <cuda_bf16.h>
#include <math.h>

#define NBATCH 16
#define CI 32
#define CO 64
#define HH 128
#define WW 128
#define DS 5
#define KK 800     // CI*DS*DS
#define BS 100     // Cholesky panel
#define SB 20      // potrf sub-block
#define NSTEP 8    // KK/BS
#define NBH 8      // batches per stream

// ---------------- scratch ----------
__device__ float g_R[NBATCH][CI][CI][9][9];
__device__ float g_Q[NBATCH][KK][KK];
__device__ float g_P[NBATCH][KK][CO];
__device__ float g_Linv[NSTEP][NBATCH][BS][BS];

// ===========================================================================
// Kernel 1 (v4): gram
// ===========================================================================
__global__ __launch_bounds__(256) void gram_kernel(const float* __restrict__ x)
{
    int n = blockIdx.y;
    int p = blockIdx.x;
    int a = 0, rem = p;
    while (rem >= CI - a) { rem -= CI - a; a++; }
    int b = a + rem;

    const float* __restrict__ xa = x + ((size_t)n * CI + a) * (HH * WW);
    const float* __restrict__ xb = x + ((size_t)n * CI + b) * (HH * WW);

    __shared__ float sxa[32][132];
    __shared__ float sxb[40][148];
    __shared__ float sred[8][81];

    int tid  = threadIdx.x;
    int lane = tid & 31;
    int wid  = tid >> 5;
    int ty = (tid & 1) + 2 * (tid >> 5);
    int tx = (tid >> 1) & 15;
    int c0 = tx * 8;

    for (int i = tid; i < 40 * 5; i += 256) {
        int rr = i / 5, e = i - rr * 5;
        int col = (e < 2) ? e * 4 : 136 + (e - 2) * 4;
        *(float4*)(&sxb[rr][col]) = make_float4(0.f, 0.f, 0.f, 0.f);
    }

    float acc[81];
#pragma unroll
    for (int q = 0; q < 81; q++) acc[q] = 0.f;

    for (int s = 0; s < 4; s++) {
        int r0 = s * 32;
        for (int i = tid; i < 1024; i += 256) {
            int rr = i >> 5, q = i & 31;
            *(float4*)(&sxa[rr][q * 4]) =
                *((const float4*)(xa + (size_t)(r0 + rr) * WW) + q);
        }
        for (int i = tid; i < 1280; i += 256) {
            int rr = i >> 5, q = i & 31;
            int gr = r0 + rr - 4;
            float4 v = make_float4(0.f, 0.f, 0.f, 0.f);
            if (gr >= 0 && gr < HH)
                v = *((const float4*)(xb + (size_t)gr * WW) + q);
            *(float4*)(&sxb[rr][8 + q * 4]) = v;
        }
        __syncthreads();

#pragma unroll
        for (int half = 0; half < 2; half++) {
            int r = ty + half * 16;
            float xav[8];
            {
                const float4* rowp = (const float4*)(&sxa[r][c0]);
                float4 v0 = rowp[0], v1 = rowp[1];
                xav[0] = v0.x; xav[1] = v0.y; xav[2] = v0.z; xav[3] = v0.w;
                xav[4] = v1.x; xav[5] = v1.y; xav[6] = v1.z; xav[7] = v1.w;
            }
#pragma unroll
            for (int du = 0; du < 9; du++) {
                float xbv[16];
                const float4* row = (const float4*)(&sxb[r + du][c0 + 4]);
#pragma unroll
                for (int q4 = 0; q4 < 4; q4++) {
                    float4 v = row[q4];
                    xbv[q4 * 4 + 0] = v.x; xbv[q4 * 4 + 1] = v.y;
                    xbv[q4 * 4 + 2] = v.z; xbv[q4 * 4 + 3] = v.w;
                }
#pragma unroll
                for (int t = 0; t < 8; t++)
#pragma unroll
                    for (int dv = 0; dv < 9; dv++)
                        acc[du * 9 + dv] += xav[t] * xbv[t + dv];
            }
        }
        __syncthreads();
    }

#pragma unroll
    for (int q = 0; q < 81; q++) {
        float v = acc[q];
        for (int o = 16; o; o >>= 1) v += __shfl_down_sync(0xffffffffu, v, o);
        if (lane == 0) sred[wid][q] = v;
    }
    __syncthreads();
    if (tid < 81) {
        float v = 0.f;
#pragma unroll
        for (int w = 0; w < 8; w++) v += sred[w][tid];
        int u = tid / 9, vv = tid - u * 9;
        g_R[n][a][b][u][vv] = v;
        g_R[n][b][a][8 - u][8 - vv] = v;
    }
}

// ===========================================================================
// Kernel 2 (v5): scorr — yavAll hoisted to registers, xraw loaded once per du
// ===========================================================================
__global__ __launch_bounds__(256) void scorr_kernel(const float* __restrict__ x,
                                                    const float* __restrict__ y,
                                                    const float* __restrict__ d,
                                                    const float* __restrict__ alpha,
                                                    const float* __restrict__ regp)
{
    int n  = blockIdx.y;
    int b  = blockIdx.x & 31;
    int o0 = (blockIdx.x >> 5) * 4;

    const float* __restrict__ xb = x + ((size_t)n * CI + b) * (HH * WW);
    const float* __restrict__ yb = y + ((size_t)n * CO + o0) * (HH * WW);

    __shared__ float sya[4][16][132];
    __shared__ float sxb[20][148];
    __shared__ float sred[8][100];

    int tid  = threadIdx.x;
    int lane = tid & 31;
    int wid  = tid >> 5;
    int ty = (tid & 1) + 2 * (tid >> 5);
    int tx = (tid >> 1) & 15;
    int c0 = tx * 8;
    int fy = tid >> 4, fx = tid & 15;

    for (int i = tid; i < 20 * 5; i += 256) {
        int rr = i / 5, e = i - rr * 5;
        int col = (e < 2) ? e * 4 : 136 + (e - 2) * 4;
        *(float4*)(&sxb[rr][col]) = make_float4(0.f, 0.f, 0.f, 0.f);
    }

    float acc[100];
#pragma unroll
    for (int q = 0; q < 100; q++) acc[q] = 0.f;

    for (int s = 0; s < 8; s++) {
        int r0 = s * 16;
#pragma unroll
        for (int o = 0; o < 4; o++) {
            const float4* src = (const float4*)(yb + (size_t)o * (HH * WW) + (size_t)(r0 + fy) * WW);
            float4* dst = (float4*)(&sya[o][fy][0]);
            dst[fx * 2]     = src[fx * 2];
            dst[fx * 2 + 1] = src[fx * 2 + 1];
        }
        for (int i = tid; i < 640; i += 256) {
            int rr = i >> 5, q = i & 31;
            int gr = r0 + rr - 2;
            float4 v = make_float4(0.f, 0.f, 0.f, 0.f);
            if (gr >= 0 && gr < HH)
                v = *((const float4*)(xb + (size_t)gr * WW) + q);
            *(float4*)(&sxb[rr][8 + q * 4]) = v;
        }
        __syncthreads();

        // hoist all 4 o-channel pixel vectors into registers once per stripe
        float yavAll[4][8];
#pragma unroll
        for (int o = 0; o < 4; o++) {
            const float4* rowp = (const float4*)(&sya[o][ty][c0]);
            float4 v0 = rowp[0], v1 = rowp[1];
            yavAll[o][0] = v0.x; yavAll[o][1] = v0.y;
            yavAll[o][2] = v0.z; yavAll[o][3] = v0.w;
            yavAll[o][4] = v1.x; yavAll[o][5] = v1.y;
            yavAll[o][6] = v1.z; yavAll[o][7] = v1.w;
        }

#pragma unroll
        for (int du = 0; du < 5; du++) {
            float xraw[16];
            const float4* row = (const float4*)(&sxb[ty + du][c0 + 4]);
#pragma unroll
            for (int q4 = 0; q4 < 4; q4++) {
                float4 v = row[q4];
                xraw[q4 * 4 + 0] = v.x; xraw[q4 * 4 + 1] = v.y;
                xraw[q4 * 4 + 2] = v.z; xraw[q4 * 4 + 3] = v.w;
            }
#pragma unroll
            for (int o = 0; o < 4; o++)
#pragma unroll
                for (int t = 0; t < 8; t++)
#pragma unroll
                    for (int dv = 0; dv < 5; dv++)
                        acc[o * 25 + du * 5 + dv] += yavAll[o][t] * xraw[t + dv + 2];
        }
        __syncthreads();
    }

#pragma unroll
    for (int q = 0; q < 100; q++) {
        float v = acc[q];
        for (int oo = 16; oo; oo >>= 1) v += __shfl_down_sync(0xffffffffu, v, oo);
        if (lane == 0) sred[wid][q] = v;
    }
    __syncthreads();
    if (tid < 100) {
        float v = 0.f;
#pragma unroll
        for (int w = 0; w < 8; w++) v += sred[w][tid];
        int o = tid / 25, q = tid - o * 25;
        int k = b * 25 + q;
        float an = alpha[n] * ((float)(HH * WW) * regp[0] / (float)(DS * DS * CI));
        g_P[n][k][o0 + o] = v + an * d[((size_t)n * CO + o0 + o) * KK + k];
    }
}

// ===========================================================================
// Kernel 3 (v2): assembleQ
// ===========================================================================
__global__ __launch_bounds__(256) void assembleQ_kernel(const float* __restrict__ alpha,
                                                        const float* __restrict__ regp)
{
    int n = blockIdx.y;
    int a = blockIdx.x;
    __shared__ float Rs[CI][81];

    int tid = threadIdx.x;
    const float* rsrc = &g_R[n][a][0][0][0];
    for (int i = tid; i < CI * 81; i += 256)
        Rs[i / 81][i - (i / 81) * 81] = rsrc[i];
    __syncthreads();

    float an = alpha[n] * ((float)(HH * WW) * regp[0] / (float)(DS * DS * CI));
#pragma unroll
    for (int r = 0; r < 5; r++) {
#pragma unroll
        for (int s5 = 0; s5 < 5; s5++) {
            int k1 = a * 25 + r * 5 + s5;
            for (int k2 = tid; k2 <= k1; k2 += 256) {
                int bb = k2 / 25, rm = k2 - bb * 25;
                int pp = rm / 5, tt = rm - pp * 5;
                float v = Rs[bb][(pp - r + 4) * 9 + (tt - s5 + 4)];
                if (k2 == k1) v += an;
                g_Q[n][k1][k2] = v;
            }
        }
    }
}

// ===========================================================================
// potrf v5 (+nbase)
// ===========================================================================
__global__ __launch_bounds__(256) void potrf_kernel(int k0, int s, int nbase)
{
    int n = nbase + blockIdx.x;
    extern __shared__ float sh[];
    float (*A)[BS + 1] = (float(*)[BS + 1])sh;
    float (*V)[BS + 1] = (float(*)[BS + 1])(sh + BS * (BS + 1));
    __shared__ float dinv[BS];
    __shared__ float colb[32];
    __shared__ float Dv[5][SB][SB];
    __shared__ float Bt[4][SB][SB];

    int tid  = threadIdx.x;
    int lane = tid & 31;
    int wid  = tid >> 5;

    for (int idx = tid; idx < BS * BS; idx += 256) {
        int i = idx / BS, j = idx - i * BS;
        A[i][j] = g_Q[n][k0 + i][k0 + j];
    }
    __syncthreads();

    for (int p = 0; p < BS / SB; p++) {
        int c0 = p * SB;

        if (wid == 0) {
            float r[SB];
            if (lane < SB) {
#pragma unroll
                for (int j = 0; j < SB; j++) r[j] = A[c0 + lane][c0 + j];
            }
#pragma unroll
            for (int j = 0; j < SB; j++) {
                float ajj = __shfl_sync(0xffffffffu, r[j], j);
                float dd = rsqrtf(ajj);
                if (lane == j) dinv[c0 + j] = dd;
                if (lane >= j && lane < SB) r[j] *= dd;
                colb[lane] = r[j];
                __syncwarp();
#pragma unroll
                for (int k = j + 1; k < SB; k++)
                    if (lane >= k) r[k] -= r[j] * colb[k];
                __syncwarp();
            }
            if (lane < SB) {
#pragma unroll
                for (int j = 0; j < SB; j++)
                    if (j <= lane) A[c0 + lane][c0 + j] = r[j];
            }
        }
        __syncthreads();

        if (wid == 0) {
            if (lane < SB) {
                int c = lane;
                float w[SB];
#pragma unroll
                for (int r2 = 0; r2 < SB; r2++) {
                    float t = (r2 == c) ? 1.f : 0.f;
#pragma unroll
                    for (int m = 0; m < SB; m++)
                        if (m < r2) t -= A[c0 + r2][c0 + m] * w[m];
                    w[r2] = t * dinv[c0 + r2];
                }
#pragma unroll
                for (int r2 = 0; r2 < SB; r2++) Dv[p][r2][c] = w[r2];
            }
        } else {
            int rr = c0 + SB + (tid - 32);
            if (rr < BS) {
                float v[SB];
#pragma unroll
                for (int j = 0; j < SB; j++) v[j] = A[rr][c0 + j];
#pragma unroll
                for (int j = 0; j < SB; j++) {
                    float t = v[j];
#pragma unroll
                    for (int m = 0; m < SB; m++)
                        if (m < j) t -= A[c0 + j][c0 + m] * v[m];
                    v[j] = t * dinv[c0 + j];
                }
#pragma unroll
                for (int j = 0; j < SB; j++) A[rr][c0 + j] = v[j];
            }
        }
        __syncthreads();

        int m = BS - c0 - SB;
        if (m > 0) {
            int tr = tid >> 4, tc = tid & 15;
            float c[5][5];
#pragma unroll
            for (int i = 0; i < 5; i++)
#pragma unroll
                for (int j = 0; j < 5; j++) c[i][j] = 0.f;
#pragma unroll
            for (int k = 0; k < SB; k++) {
                float ra[5], rb[5];
#pragma unroll
                for (int ii = 0; ii < 5; ii++) {
                    int row = c0 + SB + tr + ii * 16;
                    ra[ii] = (row < BS) ? A[row][c0 + k] : 0.f;
                }
#pragma unroll
                for (int jj = 0; jj < 5; jj++) {
                    int col = c0 + SB + tc + jj * 16;
                    rb[jj] = (col < BS) ? A[col][c0 + k] : 0.f;
                }
#pragma unroll
                for (int ii = 0; ii < 5; ii++)
#pragma unroll
                    for (int jj = 0; jj < 5; jj++)
                        c[ii][jj] += ra[ii] * rb[jj];
            }
#pragma unroll
            for (int ii = 0; ii < 5; ii++) {
                int row = c0 + SB + tr + ii * 16;
                if (row < BS) {
#pragma unroll
                    for (int jj = 0; jj < 5; jj++) {
                        int col = c0 + SB + tc + jj * 16;
                        if (col < BS) A[row][col] -= c[ii][jj];
                    }
                }
            }
        }
        __syncthreads();
    }

    for (int idx = tid; idx < 5 * SB * SB; idx += 256) {
        int q = idx / (SB * SB), r2 = (idx / SB) % SB, cc = idx % SB;
        V[q * SB + r2][q * SB + cc] = Dv[q][r2][cc];
    }
    __syncthreads();
    for (int p = 1; p < BS / SB; p++) {
        for (int idx = tid; idx < p * SB * SB; idx += 256) {
            int q = idx / (SB * SB), r2 = (idx / SB) % SB, cc = idx % SB;
            float t = 0.f;
            for (int mm = q; mm < p; mm++) {
#pragma unroll
                for (int k = 0; k < SB; k++)
                    t += A[p * SB + r2][mm * SB + k] * V[mm * SB + k][q * SB + cc];
            }
            Bt[q][r2][cc] = t;
        }
        __syncthreads();
        for (int idx = tid; idx < p * SB * SB; idx += 256) {
            int q = idx / (SB * SB), r2 = (idx / SB) % SB, cc = idx % SB;
            float t = 0.f;
#pragma unroll
            for (int k = 0; k < SB; k++)
                t += Dv[p][r2][k] * Bt[q][k][cc];
            V[p * SB + r2][q * SB + cc] = -t;
        }
        __syncthreads();
    }

    for (int idx = tid; idx < BS * BS; idx += 256) {
        int i = idx / BS, j = idx - i * BS;
        if (j <= i) g_Q[n][k0 + i][k0 + j] = A[i][j];
        g_Linv[s][n][i][j] = (j <= i) ? V[i][j] : 0.f;
    }
}

// ===========================================================================
// trsm as GEMM (fused: Q tiles + P panel), +nbase
// ===========================================================================
__global__ __launch_bounds__(256) void trsm_gemm(int k0, int s, int nbase)
{
    int n = nbase + blockIdx.y;
    int p = blockIdx.x;
    int rows = KK - k0 - BS;
    int rowTiles = (rows + 63) >> 6;

    extern __shared__ float sh[];
    float (*Li)[BS + 1] = (float(*)[BS + 1])sh;

    int tid = threadIdx.x;
    int tr = tid >> 4, tc = tid & 15;

    for (int idx = tid; idx < BS * BS; idx += 256) {
        int i = idx / BS, j = idx - i * BS;
        Li[i][j] = g_Linv[s][n][i][j];
    }

    if (p < rowTiles) {
        float (*Ta)[BS + 1] = (float(*)[BS + 1])(sh + BS * (BS + 1));
        int rbase = k0 + BS + p * 64;
        for (int idx = tid; idx < 64 * BS; idx += 256) {
            int rr = idx / BS, k = idx - rr * BS;
            Ta[rr][k] = (rbase + rr < KK) ? g_Q[n][rbase + rr][k0 + k] : 0.f;
        }
        __syncthreads();

        float c[4][7];
#pragma unroll
        for (int i = 0; i < 4; i++)
#pragma unroll
            for (int j = 0; j < 7; j++) c[i][j] = 0.f;
#pragma unroll 4
        for (int k = 0; k < BS; k++) {
            float ra[4], rb[7];
#pragma unroll
            for (int ii = 0; ii < 4; ii++) ra[ii] = Ta[tr + 16 * ii][k];
#pragma unroll
            for (int jj = 0; jj < 7; jj++) {
                int j = tc + 16 * jj;
                rb[jj] = (j < BS) ? Li[j][k] : 0.f;
            }
#pragma unroll
            for (int ii = 0; ii < 4; ii++)
#pragma unroll
                for (int jj = 0; jj < 7; jj++)
                    c[ii][jj] += ra[ii] * rb[jj];
        }
#pragma unroll
        for (int ii = 0; ii < 4; ii++) {
            int gr = rbase + tr + 16 * ii;
            if (gr < KK) {
#pragma unroll
                for (int jj = 0; jj < 7; jj++) {
                    int j = tc + 16 * jj;
                    if (j < BS) g_Q[n][gr][k0 + j] = c[ii][jj];
                }
            }
        }
    } else {
        float (*Tp)[CO + 1] = (float(*)[CO + 1])(sh + BS * (BS + 1));
        for (int idx = tid; idx < BS * CO; idx += 256) {
            int k = idx >> 6, cc = idx & 63;
            Tp[k][cc] = g_P[n][k0 + k][cc];
        }
        __syncthreads();

        float c[7][4];
#pragma unroll
        for (int i = 0; i < 7; i++)
#pragma unroll
            for (int j = 0; j < 4; j++) c[i][j] = 0.f;
#pragma unroll 4
        for (int k = 0; k < BS; k++) {
            float ra[7], rb[4];
#pragma unroll
            for (int ii = 0; ii < 7; ii++) {
                int i = tr + 16 * ii;
                ra[ii] = (i < BS) ? Li[i][k] : 0.f;
            }
#pragma unroll
            for (int jj = 0; jj < 4; jj++) rb[jj] = Tp[k][tc + 16 * jj];
#pragma unroll
            for (int ii = 0; ii < 7; ii++)
#pragma unroll
                for (int jj = 0; jj < 4; jj++)
                    c[ii][jj] += ra[ii] * rb[jj];
        }
#pragma unroll
        for (int ii = 0; ii < 7; ii++) {
            int i = tr + 16 * ii;
            if (i < BS) {
#pragma unroll
                for (int jj = 0; jj < 4; jj++)
                    g_P[n][k0 + i][tc + 16 * jj] = c[ii][jj];
            }
        }
    }
}

// ===========================================================================
// syrk (fused: Q lower tiles + P tiles), +nbase
// ===========================================================================
__global__ __launch_bounds__(256) void syrk_kernel(int k0, int nbase)
{
    int off = k0 + BS;
    int m = KK - off;
    int nt = (m + 63) >> 6;
    int ntri = nt * (nt + 1) / 2;
    int n = nbase + blockIdx.y;
    int p = blockIdx.x;

    __shared__ float LA[64][21];
    __shared__ float LB[64][21];
    int tid = threadIdx.x;
    int txx = tid & 15, tyy = tid >> 4;

    int ti, tj;
    bool pmode = (p >= ntri);
    if (pmode) { ti = p - ntri; tj = -1; }
    else {
        tj = 0;
        while (p >= nt - tj) { p -= nt - tj; tj++; }
        ti = tj + p;
    }

    float c[4][4];
#pragma unroll
    for (int i = 0; i < 4; i++)
#pragma unroll
        for (int j = 0; j < 4; j++) c[i][j] = 0.f;

    int rbase = off + ti * 64;
    int cbase = pmode ? 0 : off + tj * 64;

    for (int kk = 0; kk < BS; kk += 20) {
        for (int idx = tid; idx < 64 * 20; idx += 256) {
            int rr = idx / 20, k = idx - rr * 20;
            LA[rr][k] = (rbase + rr < KK) ? g_Q[n][rbase + rr][k0 + kk + k] : 0.f;
        }
        if (pmode) {
            for (int idx = tid; idx < 20 * 64; idx += 256) {
                int k = idx >> 6, cc = idx & 63;
                LB[cc][k] = g_P[n][k0 + kk + k][cc];
            }
        } else {
            for (int idx = tid; idx < 64 * 20; idx += 256) {
                int rr = idx / 20, k = idx - rr * 20;
                LB[rr][k] = (cbase + rr < KK) ? g_Q[n][cbase + rr][k0 + kk + k] : 0.f;
            }
        }
        __syncthreads();
#pragma unroll
        for (int k = 0; k < 20; k++) {
            float ra[4], rb[4];
#pragma unroll
            for (int i = 0; i < 4; i++) ra[i] = LA[tyy * 4 + i][k];
#pragma unroll
            for (int j = 0; j < 4; j++) rb[j] = LB[txx * 4 + j][k];
#pragma unroll
            for (int i = 0; i < 4; i++)
#pragma unroll
                for (int j = 0; j < 4; j++) c[i][j] += ra[i] * rb[j];
        }
        __syncthreads();
    }
#pragma unroll
    for (int i = 0; i < 4; i++) {
        int gr = rbase + tyy * 4 + i;
        if (gr < KK) {
            if (pmode) {
#pragma unroll
                for (int j = 0; j < 4; j++)
                    g_P[n][gr][txx * 4 + j] -= c[i][j];
            } else {
#pragma unroll
                for (int j = 0; j < 4; j++) {
                    int gc = cbase + txx * 4 + j;
                    if (gc < KK) g_Q[n][gr][gc] -= c[i][j];
                }
            }
        }
    }
}

// ===========================================================================
// backward diag solve as GEMM (+nbase)
// ===========================================================================
__global__ __launch_bounds__(256) void bwd_gemm(int k0, int s, int nbase)
{
    int n = nbase + blockIdx.y;
    int half = blockIdx.x;

    extern __shared__ float sh[];
    float (*Li)[BS + 1] = (float(*)[BS + 1])sh;
    float (*Zp)[33]     = (float(*)[33])(sh + BS * (BS + 1));

    int tid = threadIdx.x;
    int tr = tid >> 4, tc = tid & 15;

    for (int idx = tid; idx < BS * BS; idx += 256) {
        int i = idx / BS, j = idx - i * BS;
        Li[i][j] = g_Linv[s][n][i][j];
    }
    for (int idx = tid; idx < BS * 32; idx += 256) {
        int k = idx >> 5, cc = idx & 31;
        Zp[k][cc] = g_P[n][k0 + k][half * 32 + cc];
    }
    __syncthreads();

    float c[7][2];
#pragma unroll
    for (int i = 0; i < 7; i++)
#pragma unroll
        for (int j = 0; j < 2; j++) c[i][j] = 0.f;
#pragma unroll 4
    for (int k = 0; k < BS; k++) {
        float ra[7], rb[2];
#pragma unroll
        for (int ii = 0; ii < 7; ii++) {
            int i = tr + 16 * ii;
            ra[ii] = (i < BS) ? Li[k][i] : 0.f;
        }
#pragma unroll
        for (int jj = 0; jj < 2; jj++) rb[jj] = Zp[k][tc + 16 * jj];
#pragma unroll
        for (int ii = 0; ii < 7; ii++)
#pragma unroll
            for (int jj = 0; jj < 2; jj++)
                c[ii][jj] += ra[ii] * rb[jj];
    }
#pragma unroll
    for (int ii = 0; ii < 7; ii++) {
        int i = tr + 16 * ii;
        if (i < BS) {
#pragma unroll
            for (int jj = 0; jj < 2; jj++)
                g_P[n][k0 + i][half * 32 + tc + 16 * jj] = c[ii][jj];
        }
    }
}

// backward update (+nbase)
__global__ __launch_bounds__(256) void bsolve_update_kernel(int k0, int nbase)
{
    int n = nbase + blockIdx.y;
    int rbase = blockIdx.x * 64;

    __shared__ float AT[20][65];
    __shared__ float BB[20][65];
    int tid = threadIdx.x;
    int txx = tid & 15, tyy = tid >> 4;

    float c[4][4];
#pragma unroll
    for (int i = 0; i < 4; i++)
#pragma unroll
        for (int j = 0; j < 4; j++) c[i][j] = 0.f;

    for (int kk = 0; kk < BS; kk += 20) {
        for (int idx = tid; idx < 20 * 64; idx += 256) {
            int k = idx >> 6, rl = idx & 63;
            AT[k][rl] = g_Q[n][k0 + kk + k][rbase + rl];
        }
        for (int idx = tid; idx < 20 * 64; idx += 256) {
            int k = idx >> 6, cc = idx & 63;
            BB[k][cc] = g_P[n][k0 + kk + k][cc];
        }
        __syncthreads();
#pragma unroll
        for (int k = 0; k < 20; k++) {
            float ra[4], rb[4];
#pragma unroll
            for (int i = 0; i < 4; i++) ra[i] = AT[k][tyy * 4 + i];
#pragma unroll
            for (int j = 0; j < 4; j++) rb[j] = BB[k][txx * 4 + j];
#pragma unroll
            for (int i = 0; i < 4; i++)
#pragma unroll
                for (int j = 0; j < 4; j++) c[i][j] += ra[i] * rb[j];
        }
        __syncthreads();
    }
#pragma unroll
    for (int i = 0; i < 4; i++) {
        int gr = rbase + tyy * 4 + i;
        if (gr < k0) {
#pragma unroll
            for (int j = 0; j < 4; j++)
                g_P[n][gr][txx * 4 + j] -= c[i][j];
        }
    }
}

// final transpose: out[n][o][k] = P[n][k][o]
__global__ __launch_bounds__(256) void output_kernel(float* __restrict__ out)
{
    __shared__ float t[32][33];
    int n  = blockIdx.z;
    int kb = blockIdx.x * 32;
    int ob = blockIdx.y * 32;
    int tx = threadIdx.x & 31, ty4 = threadIdx.x >> 5;

    for (int i = ty4; i < 32; i += 8)
        t[i][tx] = g_P[n][kb + i][ob + tx];
    __syncthreads();
    for (int i = ty4; i < 32; i += 8)
        out[((size_t)n * CO + ob + i) * KK + kb + tx] = t[tx][i];
}

// ===========================================================================
static void run_chain(cudaStream_t st, int nbase, cudaEvent_t stagEv)
{
    for (int s = 0; s < NSTEP; s++) {
        int k0 = s * BS;
        potrf_kernel<<<NBH, 256, 2 * BS * (BS + 1) * 4, st>>>(k0, s, nbase);
        if (s == 0 && stagEv) cudaEventRecord(stagEv, st);
        int rows = KK - k0 - BS;
        int rowTiles = (rows + 63) / 64;
        trsm_gemm<<<dim3(rowTiles + 1, NBH), 256, (BS * (BS + 1) + BS * (CO + 1)) * 4, st>>>(k0, s, nbase);
        if (rows > 0) {
            int nt = (rows + 63) / 64;
            int tiles = nt * (nt + 1) / 2 + nt;
            syrk_kernel<<<dim3(tiles, NBH), 256, 0, st>>>(k0, nbase);
        }
    }
    for (int s = NSTEP - 1; s >= 0; s--) {
        int k0 = s * BS;
        bwd_gemm<<<dim3(2, NBH), 256, (BS * (BS + 1) + BS * 33) * 4, st>>>(k0, s, nbase);
        if (k0 > 0)
            bsolve_update_kernel<<<dim3((k0 + 63) / 64, NBH), 256, 0, st>>>(k0, nbase);
    }
}

extern "C" void kernel_launch(void* const* d_in, const int* in_sizes, int n_in,
                              void* d_out, int out_size)
{
    const float* x     = (const float*)d_in[0];
    const float* d     = (const float*)d_in[1];
    const float* y     = (const float*)d_in[2];
    const float* alpha = (const float*)d_in[3];
    const float* regp  = (const float*)d_in[4];

    static int init_done = 0;
    static cudaStream_t st1, st2;
    static cudaEvent_t evFork, evStag, evJ1, evJ2;
    if (!init_done) {
        cudaFuncSetAttribute(potrf_kernel, cudaFuncAttributeMaxDynamicSharedMemorySize, 2 * BS * (BS + 1) * 4);
        cudaFuncSetAttribute(trsm_gemm,    cudaFuncAttributeMaxDynamicSharedMemorySize, (BS * (BS + 1) + BS * (CO + 1)) * 4);
        cudaFuncSetAttribute(bwd_gemm,     cudaFuncAttributeMaxDynamicSharedMemorySize, (BS * (BS + 1) + BS * 33) * 4);
        cudaStreamCreateWithFlags(&st1, cudaStreamNonBlocking);
        cudaStreamCreateWithFlags(&st2, cudaStreamNonBlocking);
        cudaEventCreateWithFlags(&evFork, cudaEventDisableTiming);
        cudaEventCreateWithFlags(&evStag, cudaEventDisableTiming);
        cudaEventCreateWithFlags(&evJ1,   cudaEventDisableTiming);
        cudaEventCreateWithFlags(&evJ2,   cudaEventDisableTiming);
        init_done = 1;
    }

    gram_kernel <<<dim3(528, NBATCH), 256>>>(x);
    scorr_kernel<<<dim3(512, NBATCH), 256>>>(x, y, d, alpha, regp);
    assembleQ_kernel<<<dim3(CI, NBATCH), 256>>>(alpha, regp);

    // fork two chains; stream 2 staggered by one potrf so its latency-bound
    // phases overlap stream 1's throughput phases (and vice versa)
    cudaEventRecord(evFork, 0);
    cudaStreamWaitEvent(st1, evFork, 0);
    cudaStreamWaitEvent(st2, evFork, 0);

    run_chain(st1, 0, evStag);
    cudaStreamWaitEvent(st2, evStag, 0);
    run_chain(st2, NBH, (cudaEvent_t)0);

    cudaEventRecord(evJ1, st1);
    cudaEventRecord(evJ2, st2);
    cudaStreamWaitEvent(0, evJ1, 0);
    cudaStreamWaitEvent(0, evJ2, 0);

    output_kernel<<<dim3(KK / 32, CO / 32, NBATCH), 256>>>((float*)d_out);
}